// round 15
// baseline (speedup 1.0000x reference)
#include <cuda_runtime.h>
#include <cuda_bf16.h>
#include <cstdint>

// B=2, Ldec=8192, Lenc=4096, D=1024, H=16, KV=4, HPG=4, DH=64, BLOCK=16, nb=512
constexpr int B_    = 2;
constexpr int LENC  = 4096;
constexpr int KVH   = 4;
constexpr int HPG_  = 4;
constexpr int NB_   = 512;
constexpr float SCALE_ = 0.125f;
constexpr int SPLITS = 8;
constexpr int KEYS_PER_SPLIT = LENC / SPLITS;   // 512

// ---------------------------------------------------------------------------
// Device scratch
// ---------------------------------------------------------------------------
__device__ float g_pooled [B_ * NB_ * 1024];
__device__ float g_q      [B_ * NB_ * 1024];
__device__ float g_k      [B_ * LENC * 256];
__device__ float g_v      [B_ * LENC * 256];
__device__ float g_attnout[B_ * NB_ * 1024];
// split-KV partials (unnormalized O and l; shift fixed at 0)
__device__ float g_pO[SPLITS * B_ * KVH * 2048 * 64];   // 33.5 MB
__device__ float g_pl[SPLITS * B_ * KVH * 2048];

// ---------------------------------------------------------------------------
// PTX helpers
// ---------------------------------------------------------------------------
__device__ __forceinline__ uint32_t f2tf32(float f) {
    uint32_t r;
    asm("cvt.rna.tf32.f32 %0, %1;" : "=r"(r) : "f"(f));
    return r;
}
__device__ __forceinline__ float tfr(float f) {
    return __uint_as_float(f2tf32(f));
}
__device__ __forceinline__ void mma_tf32(float* c, const uint32_t* a, const uint32_t* b) {
    asm volatile(
        "mma.sync.aligned.m16n8k8.row.col.f32.tf32.tf32.f32 "
        "{%0,%1,%2,%3},{%4,%5,%6,%7},{%8,%9},{%0,%1,%2,%3};"
        : "+f"(c[0]), "+f"(c[1]), "+f"(c[2]), "+f"(c[3])
        : "r"(a[0]), "r"(a[1]), "r"(a[2]), "r"(a[3]), "r"(b[0]), "r"(b[1]));
}
__device__ __forceinline__ void cp_async16(void* smem, const void* gmem) {
    uint32_t s = (uint32_t)__cvta_generic_to_shared(smem);
    asm volatile("cp.async.cg.shared.global [%0], [%1], 16;" :: "r"(s), "l"(gmem));
}
#define CP_COMMIT()  asm volatile("cp.async.commit_group;")
#define CP_WAIT(N)   asm volatile("cp.async.wait_group %0;" :: "n"(N))

template<int RND>
__device__ __forceinline__ uint32_t fld(const float* p) {
    return RND ? f2tf32(*p) : __float_as_uint(*p);
}

// ---------------------------------------------------------------------------
// 1) Mean-pool
// ---------------------------------------------------------------------------
__global__ void __launch_bounds__(256) pool_kernel(const float* __restrict__ x) {
    const int bn = blockIdx.x;
    const int t  = threadIdx.x;
    const float4* src = reinterpret_cast<const float4*>(x) + (size_t)bn * 16 * 256;
    float sx = 0.f, sy = 0.f, sz = 0.f, sw = 0.f;
#pragma unroll
    for (int i = 0; i < 16; i++) {
        float4 v = src[(size_t)i * 256 + t];
        sx += v.x; sy += v.y; sz += v.z; sw += v.w;
    }
    const float inv = 1.0f / 16.0f;
    float4 o = {tfr(sx * inv), tfr(sy * inv), tfr(sz * inv), tfr(sw * inv)};
    reinterpret_cast<float4*>(g_pooled)[(size_t)bn * 256 + t] = o;
}

// ---------------------------------------------------------------------------
// 2) tf32 GEMM. BM=BN=64, BK=16, 128 thr = 4 warps, 4 CTAs/SM.
// ---------------------------------------------------------------------------
constexpr int ASTR = 20;
constexpr int BSTR = 72;

template<int RNDA, int RNDB, int ROUND, int BCAST>
__global__ void __launch_bounds__(128, 4) gemm64(
    const float* __restrict__ A, const float* __restrict__ Bm,
    float* __restrict__ C, int M, int N, int K)
{
    __shared__ float As[2][64 * ASTR];
    __shared__ float Bs[2][16 * BSTR];

    const int tid  = threadIdx.x;
    const int wid  = tid >> 5, lane = tid & 31;
    const int g    = lane >> 2, t = lane & 3;
    const int wm   = (wid & 1) * 32, wn = (wid >> 1) * 32;
    const size_t m0 = (size_t)blockIdx.y * 64;
    const size_t n0 = (size_t)blockIdx.x * 64;

    const int ar = tid >> 2,  ac = (tid & 3)  * 4;
    const int br = tid >> 4,  bc = (tid & 15) * 4;

    float acc[2][4][4];
#pragma unroll
    for (int i = 0; i < 2; i++)
#pragma unroll
        for (int j = 0; j < 4; j++)
#pragma unroll
            for (int l = 0; l < 4; l++) acc[i][j][l] = 0.f;

    auto stage = [&](int s, int k0) {
        const float* Ap = A + (m0 + ar) * K + k0 + ac;
        cp_async16(&As[s][ar * ASTR + ac], Ap);
        cp_async16(&As[s][(ar + 32) * ASTR + ac], Ap + (size_t)32 * K);
        const float* Bp = Bm + (size_t)(k0 + br) * N + n0 + bc;
        cp_async16(&Bs[s][br * BSTR + bc], Bp);
        cp_async16(&Bs[s][(br + 8) * BSTR + bc], Bp + (size_t)8 * N);
        CP_COMMIT();
    };

    stage(0, 0);
    const int nk = K / 16;
    for (int kt = 0; kt < nk; kt++) {
        const int s = kt & 1;
        if (kt + 1 < nk) { stage(s ^ 1, (kt + 1) * 16); CP_WAIT(1); }
        else             { CP_WAIT(0); }
        __syncthreads();

#pragma unroll
        for (int kk = 0; kk < 2; kk++) {
            const int kb = kk * 8;
            uint32_t af[2][4];
#pragma unroll
            for (int mt = 0; mt < 2; mt++) {
                const int m = wm + mt * 16;
                af[mt][0] = fld<RNDA>(&As[s][(m + g    ) * ASTR + kb + t    ]);
                af[mt][1] = fld<RNDA>(&As[s][(m + g + 8) * ASTR + kb + t    ]);
                af[mt][2] = fld<RNDA>(&As[s][(m + g    ) * ASTR + kb + t + 4]);
                af[mt][3] = fld<RNDA>(&As[s][(m + g + 8) * ASTR + kb + t + 4]);
            }
#pragma unroll
            for (int nt = 0; nt < 4; nt++) {
                uint32_t bf[2];
                const int n = wn + nt * 8 + g;
                bf[0] = fld<RNDB>(&Bs[s][(kb + t    ) * BSTR + n]);
                bf[1] = fld<RNDB>(&Bs[s][(kb + t + 4) * BSTR + n]);
                mma_tf32(acc[0][nt], af[0], bf);
                mma_tf32(acc[1][nt], af[1], bf);
            }
        }
        __syncthreads();
    }

#pragma unroll
    for (int mt = 0; mt < 2; mt++)
#pragma unroll
        for (int nt = 0; nt < 4; nt++) {
            const size_t row = m0 + wm + mt * 16 + g;
            const size_t col = n0 + wn + nt * 8 + 2 * t;
            float2 v0, v1;
            if (ROUND) {
                v0 = {tfr(acc[mt][nt][0]), tfr(acc[mt][nt][1])};
                v1 = {tfr(acc[mt][nt][2]), tfr(acc[mt][nt][3])};
            } else {
                v0 = {acc[mt][nt][0], acc[mt][nt][1]};
                v1 = {acc[mt][nt][2], acc[mt][nt][3]};
            }
            if (BCAST) {
                float* d0 = &C[(row * 16) * N + col];
                float* d1 = &C[((row + 8) * 16) * N + col];
#pragma unroll
                for (int i = 0; i < 16; i++) {
                    *reinterpret_cast<float2*>(d0 + (size_t)i * N) = v0;
                    *reinterpret_cast<float2*>(d1 + (size_t)i * N) = v1;
                }
            } else {
                *reinterpret_cast<float2*>(&C[row * N + col])       = v0;
                *reinterpret_cast<float2*>(&C[(row + 8) * N + col]) = v1;
            }
        }
}

// ---------------------------------------------------------------------------
// 3) Split-KV attention: 16 q-rows/warp, no online max, conflict-free strides,
//    ONE barrier per chunk (stage-after-barrier, double buffer).
//    Grid (32 qtiles, KVH, B*SPLITS) = 2048 CTAs; 128 thr; 4 CTAs/SM.
// ---------------------------------------------------------------------------
constexpr int KSTR  = 68;   // (nt*8+g)*68 + dk*8+t -> bank 4g+t, conflict-free
constexpr int VSTR  = 72;   // (lk*8+t)*72 + nt*8+g -> bank 8t+g, conflict-free
constexpr int PSTR  = 36;   // g*36 + lk*8+t        -> bank 4g+t, conflict-free
constexpr int CHUNK = 32;
constexpr int NCH_S = KEYS_PER_SPLIT / CHUNK;   // 16
constexpr int ATTN_SMEM = (2 * CHUNK * KSTR + 2 * CHUNK * VSTR
                         + 4 * 16 * PSTR + 2 * CHUNK) * 4;  // 45.3 KB

__global__ void __launch_bounds__(128, 4) attn_split(const int* __restrict__ mask) {
    extern __shared__ float sm[];
    float* KsB   = sm;
    float* VsB   = KsB + 2 * CHUNK * KSTR;
    float* Ps    = VsB + 2 * CHUNK * VSTR;
    float* biasS = Ps + 4 * 16 * PSTR;

    const int tid = threadIdx.x;
    const int wid = tid >> 5, lane = tid & 31;
    const int g   = lane >> 2, t = lane & 3;
    const int z   = blockIdx.z;
    const int b   = z >> 3;                   // z / SPLITS
    const int split = z & 7;                  // z % SPLITS
    const int kvh = blockIdx.y;
    const int gr0 = blockIdx.x * 64 + wid * 16;
    const int lbase = split * KEYS_PER_SPLIT;

    const int r0 = gr0 + g, r1 = gr0 + g + 8;
    const float* q0 = g_q + ((size_t)(b * NB_ + (r0 >> 2))) * 1024 + (kvh * HPG_ + (r0 & 3)) * 64;
    const float* q1 = g_q + ((size_t)(b * NB_ + (r1 >> 2))) * 1024 + (kvh * HPG_ + (r1 & 3)) * 64;

    uint32_t qf[8][4];
#pragma unroll
    for (int dk = 0; dk < 8; dk++) {
        qf[dk][0] = __float_as_uint(q0[dk * 8 + t    ] * SCALE_);
        qf[dk][1] = __float_as_uint(q1[dk * 8 + t    ] * SCALE_);
        qf[dk][2] = __float_as_uint(q0[dk * 8 + t + 4] * SCALE_);
        qf[dk][3] = __float_as_uint(q1[dk * 8 + t + 4] * SCALE_);
    }

    float o[8][4];
#pragma unroll
    for (int nt = 0; nt < 8; nt++)
#pragma unroll
        for (int j = 0; j < 4; j++) o[nt][j] = 0.f;
    float lr0 = 0.f, lr1 = 0.f;

    const float* Kg = g_k + (size_t)b * LENC * 256 + kvh * 64;
    const float* Vg = g_v + (size_t)b * LENC * 256 + kvh * 64;
    const int* mrow = mask + (size_t)b * LENC;
    float* Pw = Ps + wid * 16 * PSTR;

    auto stage = [&](int s, int l0) {
#pragma unroll
        for (int i = 0; i < 4; i++) {
            const int idx = tid + 128 * i;
            const int r = idx >> 4;
            const int c = (idx & 15) * 4;
            cp_async16(&KsB[s * CHUNK * KSTR + r * KSTR + c], Kg + (size_t)(l0 + r) * 256 + c);
            cp_async16(&VsB[s * CHUNK * VSTR + r * VSTR + c], Vg + (size_t)(l0 + r) * 256 + c);
        }
        CP_COMMIT();
        if (tid < CHUNK) biasS[s * CHUNK + tid] = (mrow[l0 + tid] == 0) ? -1e9f : 0.0f;
    };

    stage(0, lbase);
    for (int ck = 0; ck < NCH_S; ck++) {
        const int s = ck & 1;
        // ONE barrier per chunk: wait own stage groups, then barrier proves
        // (a) buffer s fully staged+visible, (b) all warps done reading s^1
        // from chunk ck-1 -> safe to restage s^1 below.
        CP_WAIT(0);
        __syncthreads();
        if (ck + 1 < NCH_S) stage(s ^ 1, lbase + (ck + 1) * CHUNK);

        const float* Kc = KsB + s * CHUNK * KSTR;
        const float* Vc = VsB + s * CHUNK * VSTR;
        const float* bc = biasS + s * CHUNK;

        // S = Q K^T
        float sc[4][4];
#pragma unroll
        for (int nt = 0; nt < 4; nt++)
#pragma unroll
            for (int j = 0; j < 4; j++) sc[nt][j] = 0.f;
#pragma unroll
        for (int dk = 0; dk < 8; dk++) {
#pragma unroll
            for (int nt = 0; nt < 4; nt++) {
                uint32_t bf[2];
                bf[0] = __float_as_uint(Kc[(nt * 8 + g) * KSTR + dk * 8 + t    ]);
                bf[1] = __float_as_uint(Kc[(nt * 8 + g) * KSTR + dk * 8 + t + 4]);
                mma_tf32(sc[nt], qf[dk], bf);
            }
        }

        // exp (no shift), accumulate l, write P
#pragma unroll
        for (int nt = 0; nt < 4; nt++) {
            float2 bb = *reinterpret_cast<const float2*>(&bc[nt * 8 + 2 * t]);
            sc[nt][0] = __expf(sc[nt][0] + bb.x);
            sc[nt][1] = __expf(sc[nt][1] + bb.y);
            sc[nt][2] = __expf(sc[nt][2] + bb.x);
            sc[nt][3] = __expf(sc[nt][3] + bb.y);
            lr0 += sc[nt][0] + sc[nt][1];
            lr1 += sc[nt][2] + sc[nt][3];
            float2 p0 = {__uint_as_float(f2tf32(sc[nt][0])),
                         __uint_as_float(f2tf32(sc[nt][1]))};
            float2 p1 = {__uint_as_float(f2tf32(sc[nt][2])),
                         __uint_as_float(f2tf32(sc[nt][3]))};
            *reinterpret_cast<float2*>(&Pw[(g    ) * PSTR + nt * 8 + 2 * t]) = p0;
            *reinterpret_cast<float2*>(&Pw[(g + 8) * PSTR + nt * 8 + 2 * t]) = p1;
        }
        __syncwarp();

        // O += P @ V
#pragma unroll
        for (int lk = 0; lk < 4; lk++) {
            uint32_t af[4];
            af[0] = __float_as_uint(Pw[(g    ) * PSTR + lk * 8 + t    ]);
            af[1] = __float_as_uint(Pw[(g + 8) * PSTR + lk * 8 + t    ]);
            af[2] = __float_as_uint(Pw[(g    ) * PSTR + lk * 8 + t + 4]);
            af[3] = __float_as_uint(Pw[(g + 8) * PSTR + lk * 8 + t + 4]);
#pragma unroll
            for (int nt = 0; nt < 8; nt++) {
                uint32_t bf[2];
                bf[0] = __float_as_uint(Vc[(lk * 8 + t    ) * VSTR + nt * 8 + g]);
                bf[1] = __float_as_uint(Vc[(lk * 8 + t + 4) * VSTR + nt * 8 + g]);
                mma_tf32(o[nt], af, bf);
            }
        }
    }

    // epilogue: reduce l across quad, store partials
    lr0 += __shfl_xor_sync(0xffffffffu, lr0, 1);
    lr0 += __shfl_xor_sync(0xffffffffu, lr0, 2);
    lr1 += __shfl_xor_sync(0xffffffffu, lr1, 1);
    lr1 += __shfl_xor_sync(0xffffffffu, lr1, 2);

    const size_t base = (((size_t)split * B_ + b) * KVH + kvh) * 2048;
    float* pO0 = g_pO + (base + r0) * 64;
    float* pO1 = g_pO + (base + r1) * 64;
#pragma unroll
    for (int nt = 0; nt < 8; nt++) {
        float2 v0 = {o[nt][0], o[nt][1]};
        float2 v1 = {o[nt][2], o[nt][3]};
        *reinterpret_cast<float2*>(&pO0[nt * 8 + 2 * t]) = v0;
        *reinterpret_cast<float2*>(&pO1[nt * 8 + 2 * t]) = v1;
    }
    if (t == 0) {
        g_pl[base + r0] = lr0;
        g_pl[base + r1] = lr1;
    }
}

// ---------------------------------------------------------------------------
// 3b) Combine: out = (Σ_split O) / (Σ_split l)
// ---------------------------------------------------------------------------
__global__ void __launch_bounds__(256) combine_kernel() {
    const int idx = blockIdx.x * 256 + threadIdx.x;
    const int row = idx >> 4;
    const int d4  = idx & 15;
    const int b   = row >> 13;
    const int rem = row & 8191;
    const int kvh = rem >> 11;
    const int r   = rem & 2047;

    const size_t stride = (size_t)B_ * KVH * 2048;
    const size_t base0  = ((size_t)b * KVH + kvh) * 2048 + r;

    float L = 0.f;
#pragma unroll
    for (int i = 0; i < SPLITS; i++) L += g_pl[i * stride + base0];
    const float invL = 1.0f / L;

    float4 acc = {0.f, 0.f, 0.f, 0.f};
#pragma unroll
    for (int i = 0; i < SPLITS; i++) {
        const float4 v = *reinterpret_cast<const float4*>(
            &g_pO[(i * stride + base0) * 64 + d4 * 4]);
        acc.x += v.x; acc.y += v.y; acc.z += v.z; acc.w += v.w;
    }
    float4 outv = {tfr(acc.x * invL), tfr(acc.y * invL),
                   tfr(acc.z * invL), tfr(acc.w * invL)};
    const int n = r >> 2, qh = r & 3;
    *reinterpret_cast<float4*>(
        &g_attnout[((size_t)(b * NB_ + n)) * 1024 + (kvh * HPG_ + qh) * 64 + d4 * 4]) = outv;
}

// ---------------------------------------------------------------------------
// Launch
// ---------------------------------------------------------------------------
extern "C" void kernel_launch(void* const* d_in, const int* in_sizes, int n_in,
                              void* d_out, int out_size) {
    (void)in_sizes; (void)n_in; (void)out_size;
    const float* hidden = (const float*)d_in[0];
    const float* enc    = (const float*)d_in[1];
    const int*   mask   = (const int*)d_in[2];
    const float* Wq     = (const float*)d_in[3];
    const float* Wk     = (const float*)d_in[4];
    const float* Wv     = (const float*)d_in[5];
    const float* Wo     = (const float*)d_in[6];
    float* out = (float*)d_out;

    float *pooled, *q, *k, *v, *attnout;
    cudaGetSymbolAddress((void**)&pooled,  g_pooled);
    cudaGetSymbolAddress((void**)&q,       g_q);
    cudaGetSymbolAddress((void**)&k,       g_k);
    cudaGetSymbolAddress((void**)&v,       g_v);
    cudaGetSymbolAddress((void**)&attnout, g_attnout);

    cudaFuncSetAttribute(attn_split, cudaFuncAttributeMaxDynamicSharedMemorySize,
                         ATTN_SMEM);

    pool_kernel<<<B_ * NB_, 256>>>(hidden);
    // q projection: A pre-rounded, B cvt in-loop, output rounded
    gemm64<0, 1, 1, 0><<<dim3(1024 / 64, (B_ * NB_) / 64), 128>>>(pooled, Wq, q,
                                                                  B_ * NB_, 1024, 1024);
    // k, v projections: separate 128-reg gemms (unfused — faster than kvgemm)
    gemm64<1, 1, 1, 0><<<dim3(256 / 64, (B_ * LENC) / 64), 128>>>(enc, Wk, k,
                                                                  B_ * LENC, 256, 1024);
    gemm64<1, 1, 1, 0><<<dim3(256 / 64, (B_ * LENC) / 64), 128>>>(enc, Wv, v,
                                                                  B_ * LENC, 256, 1024);
    attn_split<<<dim3(32, KVH, B_ * SPLITS), 128, ATTN_SMEM>>>(mask);
    combine_kernel<<<(B_ * KVH * 2048 * 16) / 256, 256>>>();
    gemm64<0, 1, 0, 1><<<dim3(1024 / 64, (B_ * NB_) / 64), 128>>>(attnout, Wo, out,
                                                                  B_ * NB_, 1024, 1024);
}

// round 17
// speedup vs baseline: 1.0460x; 1.0460x over previous
#include <cuda_runtime.h>
#include <cuda_bf16.h>
#include <cstdint>

// B=2, Ldec=8192, Lenc=4096, D=1024, H=16, KV=4, HPG=4, DH=64, BLOCK=16, nb=512
constexpr int B_    = 2;
constexpr int LENC  = 4096;
constexpr int KVH   = 4;
constexpr int HPG_  = 4;
constexpr int NB_   = 512;
constexpr float SCALE_ = 0.125f;
constexpr int SPLITS = 8;
constexpr int KEYS_PER_SPLIT = LENC / SPLITS;   // 512

// ---------------------------------------------------------------------------
// Device scratch
// ---------------------------------------------------------------------------
__device__ float g_pooled [B_ * NB_ * 1024];
__device__ float g_q      [B_ * NB_ * 1024];
__device__ float g_k      [B_ * LENC * 256];
__device__ float g_v      [B_ * LENC * 256];
__device__ float g_attnout[B_ * NB_ * 1024];
// split-KV partials (unnormalized O and l; shift fixed at 0)
__device__ float g_pO[SPLITS * B_ * KVH * 2048 * 64];   // 33.5 MB
__device__ float g_pl[SPLITS * B_ * KVH * 2048];

// ---------------------------------------------------------------------------
// PTX helpers
// ---------------------------------------------------------------------------
__device__ __forceinline__ uint32_t f2tf32(float f) {
    uint32_t r;
    asm("cvt.rna.tf32.f32 %0, %1;" : "=r"(r) : "f"(f));
    return r;
}
__device__ __forceinline__ float tfr(float f) {
    return __uint_as_float(f2tf32(f));
}
__device__ __forceinline__ void mma_tf32(float* c, const uint32_t* a, const uint32_t* b) {
    asm volatile(
        "mma.sync.aligned.m16n8k8.row.col.f32.tf32.tf32.f32 "
        "{%0,%1,%2,%3},{%4,%5,%6,%7},{%8,%9},{%0,%1,%2,%3};"
        : "+f"(c[0]), "+f"(c[1]), "+f"(c[2]), "+f"(c[3])
        : "r"(a[0]), "r"(a[1]), "r"(a[2]), "r"(a[3]), "r"(b[0]), "r"(b[1]));
}
__device__ __forceinline__ void cp_async16(void* smem, const void* gmem) {
    uint32_t s = (uint32_t)__cvta_generic_to_shared(smem);
    asm volatile("cp.async.cg.shared.global [%0], [%1], 16;" :: "r"(s), "l"(gmem));
}
#define CP_COMMIT()  asm volatile("cp.async.commit_group;")
#define CP_WAIT(N)   asm volatile("cp.async.wait_group %0;" :: "n"(N))

template<int RND>
__device__ __forceinline__ uint32_t fld(const float* p) {
    return RND ? f2tf32(*p) : __float_as_uint(*p);
}

// ---------------------------------------------------------------------------
// 1) Mean-pool
// ---------------------------------------------------------------------------
__global__ void __launch_bounds__(256) pool_kernel(const float* __restrict__ x) {
    const int bn = blockIdx.x;
    const int t  = threadIdx.x;
    const float4* src = reinterpret_cast<const float4*>(x) + (size_t)bn * 16 * 256;
    float sx = 0.f, sy = 0.f, sz = 0.f, sw = 0.f;
#pragma unroll
    for (int i = 0; i < 16; i++) {
        float4 v = src[(size_t)i * 256 + t];
        sx += v.x; sy += v.y; sz += v.z; sw += v.w;
    }
    const float inv = 1.0f / 16.0f;
    float4 o = {tfr(sx * inv), tfr(sy * inv), tfr(sz * inv), tfr(sw * inv)};
    reinterpret_cast<float4*>(g_pooled)[(size_t)bn * 256 + t] = o;
}

// ---------------------------------------------------------------------------
// 2) tf32 GEMM. BM=BN=64, BK=16, 128 thr = 4 warps, 4 CTAs/SM.
// ---------------------------------------------------------------------------
constexpr int ASTR = 20;
constexpr int BSTR = 72;

template<int RNDA, int RNDB, int ROUND, int BCAST>
__global__ void __launch_bounds__(128, 4) gemm64(
    const float* __restrict__ A, const float* __restrict__ Bm,
    float* __restrict__ C, int M, int N, int K)
{
    __shared__ float As[2][64 * ASTR];
    __shared__ float Bs[2][16 * BSTR];

    const int tid  = threadIdx.x;
    const int wid  = tid >> 5, lane = tid & 31;
    const int g    = lane >> 2, t = lane & 3;
    const int wm   = (wid & 1) * 32, wn = (wid >> 1) * 32;
    const size_t m0 = (size_t)blockIdx.y * 64;
    const size_t n0 = (size_t)blockIdx.x * 64;

    const int ar = tid >> 2,  ac = (tid & 3)  * 4;
    const int br = tid >> 4,  bc = (tid & 15) * 4;

    float acc[2][4][4];
#pragma unroll
    for (int i = 0; i < 2; i++)
#pragma unroll
        for (int j = 0; j < 4; j++)
#pragma unroll
            for (int l = 0; l < 4; l++) acc[i][j][l] = 0.f;

    auto stage = [&](int s, int k0) {
        const float* Ap = A + (m0 + ar) * K + k0 + ac;
        cp_async16(&As[s][ar * ASTR + ac], Ap);
        cp_async16(&As[s][(ar + 32) * ASTR + ac], Ap + (size_t)32 * K);
        const float* Bp = Bm + (size_t)(k0 + br) * N + n0 + bc;
        cp_async16(&Bs[s][br * BSTR + bc], Bp);
        cp_async16(&Bs[s][(br + 8) * BSTR + bc], Bp + (size_t)8 * N);
        CP_COMMIT();
    };

    stage(0, 0);
    const int nk = K / 16;
    for (int kt = 0; kt < nk; kt++) {
        const int s = kt & 1;
        if (kt + 1 < nk) { stage(s ^ 1, (kt + 1) * 16); CP_WAIT(1); }
        else             { CP_WAIT(0); }
        __syncthreads();

#pragma unroll
        for (int kk = 0; kk < 2; kk++) {
            const int kb = kk * 8;
            uint32_t af[2][4];
#pragma unroll
            for (int mt = 0; mt < 2; mt++) {
                const int m = wm + mt * 16;
                af[mt][0] = fld<RNDA>(&As[s][(m + g    ) * ASTR + kb + t    ]);
                af[mt][1] = fld<RNDA>(&As[s][(m + g + 8) * ASTR + kb + t    ]);
                af[mt][2] = fld<RNDA>(&As[s][(m + g    ) * ASTR + kb + t + 4]);
                af[mt][3] = fld<RNDA>(&As[s][(m + g + 8) * ASTR + kb + t + 4]);
            }
#pragma unroll
            for (int nt = 0; nt < 4; nt++) {
                uint32_t bf[2];
                const int n = wn + nt * 8 + g;
                bf[0] = fld<RNDB>(&Bs[s][(kb + t    ) * BSTR + n]);
                bf[1] = fld<RNDB>(&Bs[s][(kb + t + 4) * BSTR + n]);
                mma_tf32(acc[0][nt], af[0], bf);
                mma_tf32(acc[1][nt], af[1], bf);
            }
        }
        __syncthreads();
    }

#pragma unroll
    for (int mt = 0; mt < 2; mt++)
#pragma unroll
        for (int nt = 0; nt < 4; nt++) {
            const size_t row = m0 + wm + mt * 16 + g;
            const size_t col = n0 + wn + nt * 8 + 2 * t;
            float2 v0, v1;
            if (ROUND) {
                v0 = {tfr(acc[mt][nt][0]), tfr(acc[mt][nt][1])};
                v1 = {tfr(acc[mt][nt][2]), tfr(acc[mt][nt][3])};
            } else {
                v0 = {acc[mt][nt][0], acc[mt][nt][1]};
                v1 = {acc[mt][nt][2], acc[mt][nt][3]};
            }
            if (BCAST) {
                float* d0 = &C[(row * 16) * N + col];
                float* d1 = &C[((row + 8) * 16) * N + col];
#pragma unroll
                for (int i = 0; i < 16; i++) {
                    *reinterpret_cast<float2*>(d0 + (size_t)i * N) = v0;
                    *reinterpret_cast<float2*>(d1 + (size_t)i * N) = v1;
                }
            } else {
                *reinterpret_cast<float2*>(&C[row * N + col])       = v0;
                *reinterpret_cast<float2*>(&C[(row + 8) * N + col]) = v1;
            }
        }
}

// ---------------------------------------------------------------------------
// 2b) Fused K+V projection: Ck = A@Wk, Cv = A@Wv. A fragments + enc traffic
//     shared across both outputs (reads enc ONCE).
// ---------------------------------------------------------------------------
__global__ void __launch_bounds__(128) kvgemm(
    const float* __restrict__ A, const float* __restrict__ Wk,
    const float* __restrict__ Wv, float* __restrict__ Ck, float* __restrict__ Cv)
{
    constexpr int N = 256, K = 1024;
    __shared__ float As [2][64 * ASTR];
    __shared__ float Bks[2][16 * BSTR];
    __shared__ float Bvs[2][16 * BSTR];

    const int tid  = threadIdx.x;
    const int wid  = tid >> 5, lane = tid & 31;
    const int g    = lane >> 2, t = lane & 3;
    const int wm   = (wid & 1) * 32, wn = (wid >> 1) * 32;
    const size_t m0 = (size_t)blockIdx.y * 64;
    const size_t n0 = (size_t)blockIdx.x * 64;

    const int ar = tid >> 2,  ac = (tid & 3)  * 4;
    const int br = tid >> 4,  bc = (tid & 15) * 4;

    float acck[2][4][4], accv[2][4][4];
#pragma unroll
    for (int i = 0; i < 2; i++)
#pragma unroll
        for (int j = 0; j < 4; j++)
#pragma unroll
            for (int l = 0; l < 4; l++) { acck[i][j][l] = 0.f; accv[i][j][l] = 0.f; }

    auto stage = [&](int s, int k0) {
        const float* Ap = A + (m0 + ar) * K + k0 + ac;
        cp_async16(&As[s][ar * ASTR + ac], Ap);
        cp_async16(&As[s][(ar + 32) * ASTR + ac], Ap + (size_t)32 * K);
        const size_t boff = (size_t)(k0 + br) * N + n0 + bc;
        cp_async16(&Bks[s][br * BSTR + bc], Wk + boff);
        cp_async16(&Bks[s][(br + 8) * BSTR + bc], Wk + boff + (size_t)8 * N);
        cp_async16(&Bvs[s][br * BSTR + bc], Wv + boff);
        cp_async16(&Bvs[s][(br + 8) * BSTR + bc], Wv + boff + (size_t)8 * N);
        CP_COMMIT();
    };

    stage(0, 0);
    const int nk = K / 16;
    for (int kt = 0; kt < nk; kt++) {
        const int s = kt & 1;
        if (kt + 1 < nk) { stage(s ^ 1, (kt + 1) * 16); CP_WAIT(1); }
        else             { CP_WAIT(0); }
        __syncthreads();

#pragma unroll
        for (int kk = 0; kk < 2; kk++) {
            const int kb = kk * 8;
            uint32_t af[2][4];
#pragma unroll
            for (int mt = 0; mt < 2; mt++) {
                const int m = wm + mt * 16;
                af[mt][0] = f2tf32(As[s][(m + g    ) * ASTR + kb + t    ]);
                af[mt][1] = f2tf32(As[s][(m + g + 8) * ASTR + kb + t    ]);
                af[mt][2] = f2tf32(As[s][(m + g    ) * ASTR + kb + t + 4]);
                af[mt][3] = f2tf32(As[s][(m + g + 8) * ASTR + kb + t + 4]);
            }
#pragma unroll
            for (int nt = 0; nt < 4; nt++) {
                const int n = wn + nt * 8 + g;
                uint32_t bf[2];
                bf[0] = f2tf32(Bks[s][(kb + t    ) * BSTR + n]);
                bf[1] = f2tf32(Bks[s][(kb + t + 4) * BSTR + n]);
                mma_tf32(acck[0][nt], af[0], bf);
                mma_tf32(acck[1][nt], af[1], bf);
                bf[0] = f2tf32(Bvs[s][(kb + t    ) * BSTR + n]);
                bf[1] = f2tf32(Bvs[s][(kb + t + 4) * BSTR + n]);
                mma_tf32(accv[0][nt], af[0], bf);
                mma_tf32(accv[1][nt], af[1], bf);
            }
        }
        __syncthreads();
    }

#pragma unroll
    for (int mt = 0; mt < 2; mt++)
#pragma unroll
        for (int nt = 0; nt < 4; nt++) {
            const size_t row = m0 + wm + mt * 16 + g;
            const size_t col = n0 + wn + nt * 8 + 2 * t;
            float2 k0v = {tfr(acck[mt][nt][0]), tfr(acck[mt][nt][1])};
            float2 k1v = {tfr(acck[mt][nt][2]), tfr(acck[mt][nt][3])};
            *reinterpret_cast<float2*>(&Ck[row * N + col])       = k0v;
            *reinterpret_cast<float2*>(&Ck[(row + 8) * N + col]) = k1v;
            float2 v0v = {tfr(accv[mt][nt][0]), tfr(accv[mt][nt][1])};
            float2 v1v = {tfr(accv[mt][nt][2]), tfr(accv[mt][nt][3])};
            *reinterpret_cast<float2*>(&Cv[row * N + col])       = v0v;
            *reinterpret_cast<float2*>(&Cv[(row + 8) * N + col]) = v1v;
        }
}

// ---------------------------------------------------------------------------
// 3) Split-KV attention: 16 q-rows/warp, no online max, conflict-free strides,
//    ONE barrier per chunk (stage-after-barrier, double buffer).
//    Grid (32 qtiles, KVH, B*SPLITS) = 2048 CTAs; 128 thr; 4 CTAs/SM.
// ---------------------------------------------------------------------------
constexpr int KSTR  = 68;
constexpr int VSTR  = 72;
constexpr int PSTR  = 36;
constexpr int CHUNK = 32;
constexpr int NCH_S = KEYS_PER_SPLIT / CHUNK;   // 16
constexpr int ATTN_SMEM = (2 * CHUNK * KSTR + 2 * CHUNK * VSTR
                         + 4 * 16 * PSTR + 2 * CHUNK) * 4;  // 45.3 KB

__global__ void __launch_bounds__(128, 4) attn_split(const int* __restrict__ mask) {
    extern __shared__ float sm[];
    float* KsB   = sm;
    float* VsB   = KsB + 2 * CHUNK * KSTR;
    float* Ps    = VsB + 2 * CHUNK * VSTR;
    float* biasS = Ps + 4 * 16 * PSTR;

    const int tid = threadIdx.x;
    const int wid = tid >> 5, lane = tid & 31;
    const int g   = lane >> 2, t = lane & 3;
    const int z   = blockIdx.z;
    const int b   = z >> 3;
    const int split = z & 7;
    const int kvh = blockIdx.y;
    const int gr0 = blockIdx.x * 64 + wid * 16;
    const int lbase = split * KEYS_PER_SPLIT;

    const int r0 = gr0 + g, r1 = gr0 + g + 8;
    const float* q0 = g_q + ((size_t)(b * NB_ + (r0 >> 2))) * 1024 + (kvh * HPG_ + (r0 & 3)) * 64;
    const float* q1 = g_q + ((size_t)(b * NB_ + (r1 >> 2))) * 1024 + (kvh * HPG_ + (r1 & 3)) * 64;

    uint32_t qf[8][4];
#pragma unroll
    for (int dk = 0; dk < 8; dk++) {
        qf[dk][0] = __float_as_uint(q0[dk * 8 + t    ] * SCALE_);
        qf[dk][1] = __float_as_uint(q1[dk * 8 + t    ] * SCALE_);
        qf[dk][2] = __float_as_uint(q0[dk * 8 + t + 4] * SCALE_);
        qf[dk][3] = __float_as_uint(q1[dk * 8 + t + 4] * SCALE_);
    }

    float o[8][4];
#pragma unroll
    for (int nt = 0; nt < 8; nt++)
#pragma unroll
        for (int j = 0; j < 4; j++) o[nt][j] = 0.f;
    float lr0 = 0.f, lr1 = 0.f;

    const float* Kg = g_k + (size_t)b * LENC * 256 + kvh * 64;
    const float* Vg = g_v + (size_t)b * LENC * 256 + kvh * 64;
    const int* mrow = mask + (size_t)b * LENC;
    float* Pw = Ps + wid * 16 * PSTR;

    auto stage = [&](int s, int l0) {
#pragma unroll
        for (int i = 0; i < 4; i++) {
            const int idx = tid + 128 * i;
            const int r = idx >> 4;
            const int c = (idx & 15) * 4;
            cp_async16(&KsB[s * CHUNK * KSTR + r * KSTR + c], Kg + (size_t)(l0 + r) * 256 + c);
            cp_async16(&VsB[s * CHUNK * VSTR + r * VSTR + c], Vg + (size_t)(l0 + r) * 256 + c);
        }
        CP_COMMIT();
        if (tid < CHUNK) biasS[s * CHUNK + tid] = (mrow[l0 + tid] == 0) ? -1e9f : 0.0f;
    };

    stage(0, lbase);
    for (int ck = 0; ck < NCH_S; ck++) {
        const int s = ck & 1;
        CP_WAIT(0);
        __syncthreads();
        if (ck + 1 < NCH_S) stage(s ^ 1, lbase + (ck + 1) * CHUNK);

        const float* Kc = KsB + s * CHUNK * KSTR;
        const float* Vc = VsB + s * CHUNK * VSTR;
        const float* bc = biasS + s * CHUNK;

        float sc[4][4];
#pragma unroll
        for (int nt = 0; nt < 4; nt++)
#pragma unroll
            for (int j = 0; j < 4; j++) sc[nt][j] = 0.f;
#pragma unroll
        for (int dk = 0; dk < 8; dk++) {
#pragma unroll
            for (int nt = 0; nt < 4; nt++) {
                uint32_t bf[2];
                bf[0] = __float_as_uint(Kc[(nt * 8 + g) * KSTR + dk * 8 + t    ]);
                bf[1] = __float_as_uint(Kc[(nt * 8 + g) * KSTR + dk * 8 + t + 4]);
                mma_tf32(sc[nt], qf[dk], bf);
            }
        }

#pragma unroll
        for (int nt = 0; nt < 4; nt++) {
            float2 bb = *reinterpret_cast<const float2*>(&bc[nt * 8 + 2 * t]);
            sc[nt][0] = __expf(sc[nt][0] + bb.x);
            sc[nt][1] = __expf(sc[nt][1] + bb.y);
            sc[nt][2] = __expf(sc[nt][2] + bb.x);
            sc[nt][3] = __expf(sc[nt][3] + bb.y);
            lr0 += sc[nt][0] + sc[nt][1];
            lr1 += sc[nt][2] + sc[nt][3];
            float2 p0 = {__uint_as_float(f2tf32(sc[nt][0])),
                         __uint_as_float(f2tf32(sc[nt][1]))};
            float2 p1 = {__uint_as_float(f2tf32(sc[nt][2])),
                         __uint_as_float(f2tf32(sc[nt][3]))};
            *reinterpret_cast<float2*>(&Pw[(g    ) * PSTR + nt * 8 + 2 * t]) = p0;
            *reinterpret_cast<float2*>(&Pw[(g + 8) * PSTR + nt * 8 + 2 * t]) = p1;
        }
        __syncwarp();

#pragma unroll
        for (int lk = 0; lk < 4; lk++) {
            uint32_t af[4];
            af[0] = __float_as_uint(Pw[(g    ) * PSTR + lk * 8 + t    ]);
            af[1] = __float_as_uint(Pw[(g + 8) * PSTR + lk * 8 + t    ]);
            af[2] = __float_as_uint(Pw[(g    ) * PSTR + lk * 8 + t + 4]);
            af[3] = __float_as_uint(Pw[(g + 8) * PSTR + lk * 8 + t + 4]);
#pragma unroll
            for (int nt = 0; nt < 8; nt++) {
                uint32_t bf[2];
                bf[0] = __float_as_uint(Vc[(lk * 8 + t    ) * VSTR + nt * 8 + g]);
                bf[1] = __float_as_uint(Vc[(lk * 8 + t + 4) * VSTR + nt * 8 + g]);
                mma_tf32(o[nt], af, bf);
            }
        }
    }

    lr0 += __shfl_xor_sync(0xffffffffu, lr0, 1);
    lr0 += __shfl_xor_sync(0xffffffffu, lr0, 2);
    lr1 += __shfl_xor_sync(0xffffffffu, lr1, 1);
    lr1 += __shfl_xor_sync(0xffffffffu, lr1, 2);

    const size_t base = (((size_t)split * B_ + b) * KVH + kvh) * 2048;
    float* pO0 = g_pO + (base + r0) * 64;
    float* pO1 = g_pO + (base + r1) * 64;
#pragma unroll
    for (int nt = 0; nt < 8; nt++) {
        float2 v0 = {o[nt][0], o[nt][1]};
        float2 v1 = {o[nt][2], o[nt][3]};
        *reinterpret_cast<float2*>(&pO0[nt * 8 + 2 * t]) = v0;
        *reinterpret_cast<float2*>(&pO1[nt * 8 + 2 * t]) = v1;
    }
    if (t == 0) {
        g_pl[base + r0] = lr0;
        g_pl[base + r1] = lr1;
    }
}

// ---------------------------------------------------------------------------
// 3b) Combine: out = (Σ_split O) / (Σ_split l)
// ---------------------------------------------------------------------------
__global__ void __launch_bounds__(256) combine_kernel() {
    const int idx = blockIdx.x * 256 + threadIdx.x;
    const int row = idx >> 4;
    const int d4  = idx & 15;
    const int b   = row >> 13;
    const int rem = row & 8191;
    const int kvh = rem >> 11;
    const int r   = rem & 2047;

    const size_t stride = (size_t)B_ * KVH * 2048;
    const size_t base0  = ((size_t)b * KVH + kvh) * 2048 + r;

    float L = 0.f;
#pragma unroll
    for (int i = 0; i < SPLITS; i++) L += g_pl[i * stride + base0];
    const float invL = 1.0f / L;

    float4 acc = {0.f, 0.f, 0.f, 0.f};
#pragma unroll
    for (int i = 0; i < SPLITS; i++) {
        const float4 v = *reinterpret_cast<const float4*>(
            &g_pO[(i * stride + base0) * 64 + d4 * 4]);
        acc.x += v.x; acc.y += v.y; acc.z += v.z; acc.w += v.w;
    }
    float4 outv = {tfr(acc.x * invL), tfr(acc.y * invL),
                   tfr(acc.z * invL), tfr(acc.w * invL)};
    const int n = r >> 2, qh = r & 3;
    *reinterpret_cast<float4*>(
        &g_attnout[((size_t)(b * NB_ + n)) * 1024 + (kvh * HPG_ + qh) * 64 + d4 * 4]) = outv;
}

// ---------------------------------------------------------------------------
// Launch
// ---------------------------------------------------------------------------
extern "C" void kernel_launch(void* const* d_in, const int* in_sizes, int n_in,
                              void* d_out, int out_size) {
    (void)in_sizes; (void)n_in; (void)out_size;
    const float* hidden = (const float*)d_in[0];
    const float* enc    = (const float*)d_in[1];
    const int*   mask   = (const int*)d_in[2];
    const float* Wq     = (const float*)d_in[3];
    const float* Wk     = (const float*)d_in[4];
    const float* Wv     = (const float*)d_in[5];
    const float* Wo     = (const float*)d_in[6];
    float* out = (float*)d_out;

    float *pooled, *q, *k, *v, *attnout;
    cudaGetSymbolAddress((void**)&pooled,  g_pooled);
    cudaGetSymbolAddress((void**)&q,       g_q);
    cudaGetSymbolAddress((void**)&k,       g_k);
    cudaGetSymbolAddress((void**)&v,       g_v);
    cudaGetSymbolAddress((void**)&attnout, g_attnout);

    cudaFuncSetAttribute(attn_split, cudaFuncAttributeMaxDynamicSharedMemorySize,
                         ATTN_SMEM);

    pool_kernel<<<B_ * NB_, 256>>>(hidden);
    // q projection: A pre-rounded, B cvt in-loop, output rounded
    gemm64<0, 1, 1, 0><<<dim3(1024 / 64, (B_ * NB_) / 64), 128>>>(pooled, Wq, q,
                                                                  B_ * NB_, 1024, 1024);
    // fused k+v projection (reads enc once)
    kvgemm<<<dim3(256 / 64, (B_ * LENC) / 64), 128>>>(enc, Wk, Wv, k, v);
    attn_split<<<dim3(32, KVH, B_ * SPLITS), 128, ATTN_SMEM>>>(mask);
    combine_kernel<<<(B_ * KVH * 2048 * 16) / 256, 256>>>();
    gemm64<0, 1, 0, 1><<<dim3(1024 / 64, (B_ * NB_) / 64), 128>>>(attnout, Wo, out,
                                                                  B_ * NB_, 1024, 1024);
}